// round 12
// baseline (speedup 1.0000x reference)
#include <cuda_runtime.h>
#include <cuda_bf16.h>

#define CLASS_NUM 512
#define B_ROWS    1024
#define E_ROWS    50000
#define OUT_ELEMS (B_ROWS * E_ROWS)   // 51,200,000
#define E4TOT     (E_ROWS / 4)        // 12,500 float4 per output row

#define E_TILE     64
#define E4_TILE    (E_TILE / 4)       // 16 float4
#define NCONS      ((E_ROWS + E_TILE - 1) / E_TILE)  // 782 consumer blocks
#define HR_BLOCKS  32                 // 32 blocks x 8 warps x 4 rows = 1024
#define HR_WARPS   (HR_BLOCKS * 8)    // 256 producer warps
#define NBLOCKS    (HR_BLOCKS + NCONS)

// Scratch (no device allocation allowed).
__device__ float g_hr[B_ROWS];        // hr_part[b] + bias (bias folded)
__device__ int   g_hr_ready;          // producer warps completed (0..256)
__device__ int   g_done;              // consumer blocks completed (self-reset)

// ---------------------------------------------------------------------------
// One kernel. Blocks [0, HR_BLOCKS): hr producers. Blocks [HR_BLOCKS, ...):
// e-tile consumers (tail dots -> smem, then stream the 1024-row column slab).
// Consumers spin on g_hr_ready only at phase b (~19us in; producers done ~2us
// in -> spin is free). Last consumer resets counters for graph replay.
// ---------------------------------------------------------------------------
__global__ void __launch_bounds__(256, 8)
fused_kernel(const float* __restrict__ hr,
             const float* __restrict__ tail,
             const float* __restrict__ W,
             const float* __restrict__ bias,
             float4* __restrict__ out)
{
    const int wid  = threadIdx.x >> 5;
    const int lane = threadIdx.x & 31;

    if (blockIdx.x < HR_BLOCKS) {
        // ================= producer: 4 hr rows per warp =================
        const float4* w4 = reinterpret_cast<const float4*>(W);
        const float4 c0 = __ldg(&w4[lane]);
        const float4 c1 = __ldg(&w4[lane + 32]);
        const float4 c2 = __ldg(&w4[lane + 64]);
        const float4 c3 = __ldg(&w4[lane + 96]);
        const float  bv = __ldg(bias);

        const int warp_global = blockIdx.x * 8 + wid;   // 0..255
#pragma unroll
        for (int r = 0; r < 4; r++) {
            const int row = warp_global * 4 + r;        // 0..1023
            const float4* s4 = reinterpret_cast<const float4*>(hr + (size_t)row * CLASS_NUM);
            float4 a0 = __ldg(&s4[lane]);
            float4 a1 = __ldg(&s4[lane + 32]);
            float4 a2 = __ldg(&s4[lane + 64]);
            float4 a3 = __ldg(&s4[lane + 96]);
            float sum = 0.0f;
            sum = fmaf(a0.x, c0.x, sum); sum = fmaf(a0.y, c0.y, sum);
            sum = fmaf(a0.z, c0.z, sum); sum = fmaf(a0.w, c0.w, sum);
            sum = fmaf(a1.x, c1.x, sum); sum = fmaf(a1.y, c1.y, sum);
            sum = fmaf(a1.z, c1.z, sum); sum = fmaf(a1.w, c1.w, sum);
            sum = fmaf(a2.x, c2.x, sum); sum = fmaf(a2.y, c2.y, sum);
            sum = fmaf(a2.z, c2.z, sum); sum = fmaf(a2.w, c2.w, sum);
            sum = fmaf(a3.x, c3.x, sum); sum = fmaf(a3.y, c3.y, sum);
            sum = fmaf(a3.z, c3.z, sum); sum = fmaf(a3.w, c3.w, sum);
#pragma unroll
            for (int off = 16; off > 0; off >>= 1)
                sum += __shfl_xor_sync(0xFFFFFFFFu, sum, off);
            if (lane == 0)
                g_hr[row] = sum + bv;
        }
        __threadfence();                                // release g_hr writes
        if (lane == 0)
            atomicAdd(&g_hr_ready, 1);
        return;
    }

    // ==================== consumer: one 64-wide e tile ====================
    __shared__ float s_tail[E_TILE];

    const int bid = blockIdx.x - HR_BLOCKS;             // 0..NCONS-1
    const int e0  = bid * E_TILE;

    // W2 in registers.
    const float4* w4 = reinterpret_cast<const float4*>(W + CLASS_NUM);
    const float4 c0 = __ldg(&w4[lane]);
    const float4 c1 = __ldg(&w4[lane + 32]);
    const float4 c2 = __ldg(&w4[lane + 64]);
    const float4 c3 = __ldg(&w4[lane + 96]);

    // ---- phase a: each warp computes 8 consecutive tail dots ----
#pragma unroll
    for (int r = 0; r < 8; r++) {
        const int el = wid * 8 + r;                     // 0..63
        const int e  = e0 + el;
        if (e < E_ROWS) {
            const float4* s4 = reinterpret_cast<const float4*>(tail + (size_t)e * CLASS_NUM);
            float4 a0 = __ldcs(&s4[lane]);
            float4 a1 = __ldcs(&s4[lane + 32]);
            float4 a2 = __ldcs(&s4[lane + 64]);
            float4 a3 = __ldcs(&s4[lane + 96]);
            float sum = 0.0f;
            sum = fmaf(a0.x, c0.x, sum); sum = fmaf(a0.y, c0.y, sum);
            sum = fmaf(a0.z, c0.z, sum); sum = fmaf(a0.w, c0.w, sum);
            sum = fmaf(a1.x, c1.x, sum); sum = fmaf(a1.y, c1.y, sum);
            sum = fmaf(a1.z, c1.z, sum); sum = fmaf(a1.w, c1.w, sum);
            sum = fmaf(a2.x, c2.x, sum); sum = fmaf(a2.y, c2.y, sum);
            sum = fmaf(a2.z, c2.z, sum); sum = fmaf(a2.w, c2.w, sum);
            sum = fmaf(a3.x, c3.x, sum); sum = fmaf(a3.y, c3.y, sum);
            sum = fmaf(a3.z, c3.z, sum); sum = fmaf(a3.w, c3.w, sum);
#pragma unroll
            for (int off = 16; off > 0; off >>= 1)
                sum += __shfl_xor_sync(0xFFFFFFFFu, sum, off);
            if (lane == 0)
                s_tail[el] = sum;
        }
    }
    __syncthreads();

    // ---- wait for hr producers (normally already done) ----
    if (threadIdx.x == 0) {
        while (atomicAdd(&g_hr_ready, 0) < HR_WARPS) { }
    }
    __syncthreads();                                    // acquire: orders g_hr reads

    // ---- phase b: stream the 1024-row x 64-col slab ----
    const int e4l  = threadIdx.x & 15;                  // 0..15
    const int brow = threadIdx.x >> 4;                  // 0..15
    const int e4g  = bid * E4_TILE + e4l;

    if (e4g < E4TOT) {
        const float4 t = *reinterpret_cast<const float4*>(&s_tail[e4l * 4]);
        float4* dst = out + (size_t)brow * E4TOT + e4g;
#pragma unroll 4
        for (int b = brow; b < B_ROWS; b += 16) {
            const float h = g_hr[b];                    // plain load (coherent via spin)
            float4 v;
            v.x = h + t.x;
            v.y = h + t.y;
            v.z = h + t.z;
            v.w = h + t.w;
            __stcs(dst, v);                             // evict-first streaming store
            dst += 16 * E4TOT;
        }
    }

    // ---- self-reset for the next graph replay ----
    __syncthreads();
    if (threadIdx.x == 0) {
        __threadfence();
        int d = atomicAdd(&g_done, 1);
        if (d == NCONS - 1) {
            g_hr_ready = 0;
            g_done = 0;
            __threadfence();
        }
    }
}

// Zero any trailing elements beyond the scores matrix.
__global__ void zero_tail_kernel(float* __restrict__ out, int start, int total)
{
    int i = start + blockIdx.x * blockDim.x + threadIdx.x;
    if (i < total) out[i] = 0.0f;
}

extern "C" void kernel_launch(void* const* d_in, const int* in_sizes, int n_in,
                              void* d_out, int out_size)
{
    const float* hr   = (const float*)d_in[0];  // [1024, 512]
    const float* tail = (const float*)d_in[1];  // [50000, 512]
    const float* W    = (const float*)d_in[2];  // [1, 1024]
    const float* bias = (const float*)d_in[3];  // [1]
    float* out = (float*)d_out;

    fused_kernel<<<NBLOCKS, 256>>>(hr, tail, W, bias, (float4*)out);

    if (out_size > OUT_ELEMS) {
        int extra = out_size - OUT_ELEMS;
        zero_tail_kernel<<<(extra + 255) / 256, 256>>>(out, OUT_ELEMS, out_size);
    }
}

// round 13
// speedup vs baseline: 1.0446x; 1.0446x over previous
#include <cuda_runtime.h>
#include <cuda_bf16.h>

#define CLASS_NUM 512
#define B_ROWS    1024
#define E_ROWS    50000
#define OUT_ELEMS (B_ROWS * E_ROWS)   // 51,200,000
#define E4        (E_ROWS / 4)        // 12,500 float4 per output row

// Row-chunking for the outer kernel: each thread handles one e4 and a chunk
// of rows, so g_tail is read exactly once from L2 instead of 1024 times.
#define ROW_CHUNK 64
#define NUM_CHUNKS (B_ROWS / ROW_CHUNK)   // 16

// Scratch (no device allocation allowed): row partial sums.
__device__ float g_hr[B_ROWS];     // hr_part[b] + bias  (bias folded here)
__device__ float g_tail[E_ROWS];   // tail_part[e]

// ---------------------------------------------------------------------------
// Kernel 1: warp-per-row dot products.
// rows [0, B_ROWS)             -> g_hr[row]   = dot(hr[row],   W[0:512]) + b
// rows [B_ROWS, B_ROWS+E_ROWS) -> g_tail[r-B] = dot(tail[r-B], W[512:1024])
// Each row = 512 floats = 128 float4; 32 lanes x 4 float4 each.
// tail is streamed (never reused) -> __ldcs to avoid L2 pollution.
// Also zeroes any output elements beyond the scores matrix (folded here to
// avoid a separate 3.5us launch).
// ---------------------------------------------------------------------------
__global__ void __launch_bounds__(256)
dot_kernel(const float* __restrict__ hr,
           const float* __restrict__ tail,
           const float* __restrict__ W,
           const float* __restrict__ bias,
           float* __restrict__ out_extra,   // out + OUT_ELEMS
           int extra)                        // out_size - OUT_ELEMS (>= 0)
{
    const int gtid    = blockIdx.x * blockDim.x + threadIdx.x;
    const int warp_id = gtid >> 5;
    const int lane    = threadIdx.x & 31;

    // Folded trailing-zero write (normally extra == 1).
    if (gtid < extra)
        out_extra[gtid] = 0.0f;

    const int total_rows = B_ROWS + E_ROWS;
    if (warp_id >= total_rows) return;

    float sum = 0.0f;

    if (warp_id < B_ROWS) {
        const float4* s4 = reinterpret_cast<const float4*>(hr + (size_t)warp_id * CLASS_NUM);
        const float4* w4 = reinterpret_cast<const float4*>(W);
#pragma unroll
        for (int k = 0; k < 4; k++) {
            int j = lane + k * 32;
            float4 a = __ldg(&s4[j]);
            float4 c = __ldg(&w4[j]);
            sum = fmaf(a.x, c.x, sum);
            sum = fmaf(a.y, c.y, sum);
            sum = fmaf(a.z, c.z, sum);
            sum = fmaf(a.w, c.w, sum);
        }
    } else {
        const float4* s4 = reinterpret_cast<const float4*>(tail + (size_t)(warp_id - B_ROWS) * CLASS_NUM);
        const float4* w4 = reinterpret_cast<const float4*>(W + CLASS_NUM);
#pragma unroll
        for (int k = 0; k < 4; k++) {
            int j = lane + k * 32;
            float4 a = __ldcs(&s4[j]);   // streaming read, evict-first
            float4 c = __ldg(&w4[j]);
            sum = fmaf(a.x, c.x, sum);
            sum = fmaf(a.y, c.y, sum);
            sum = fmaf(a.z, c.z, sum);
            sum = fmaf(a.w, c.w, sum);
        }
    }

#pragma unroll
    for (int off = 16; off > 0; off >>= 1)
        sum += __shfl_xor_sync(0xFFFFFFFFu, sum, off);

    if (lane == 0) {
        if (warp_id < B_ROWS)
            g_hr[warp_id] = sum + __ldg(bias);
        else
            g_tail[warp_id - B_ROWS] = sum;
    }
}

// ---------------------------------------------------------------------------
// Kernel 2: broadcast outer sum, LOOP-INVERTED.
// Each thread owns one float4 of tail_part (read ONCE into a register),
// then streams out[b][e4] = g_hr[b] + t for a 64-row chunk of b.
// L2 read traffic: 205 MB -> ~0.2 MB. Output stored with __stcs (evict-first).
//
// grid: x covers e4 tiles (ceil(12500/256)=49), y covers row chunks (16).
// ---------------------------------------------------------------------------
__global__ void __launch_bounds__(256)
outer_kernel(float4* __restrict__ out)
{
    __shared__ float sh_hr[ROW_CHUNK];

    const int row0 = blockIdx.y * ROW_CHUNK;
    if (threadIdx.x < ROW_CHUNK)
        sh_hr[threadIdx.x] = g_hr[row0 + threadIdx.x];
    __syncthreads();

    const int e4 = blockIdx.x * blockDim.x + threadIdx.x;
    if (e4 >= E4) return;

    const float4 t = *((const float4*)g_tail + e4);

    float4* dst = out + (size_t)row0 * E4 + e4;
#pragma unroll 4
    for (int r = 0; r < ROW_CHUNK; r++) {
        const float h = sh_hr[r];
        float4 v;
        v.x = h + t.x;
        v.y = h + t.y;
        v.z = h + t.z;
        v.w = h + t.w;
        __stcs(dst, v);              // streaming store, evict-first
        dst += E4;
    }
}

extern "C" void kernel_launch(void* const* d_in, const int* in_sizes, int n_in,
                              void* d_out, int out_size)
{
    const float* hr   = (const float*)d_in[0];  // [1024, 512]
    const float* tail = (const float*)d_in[1];  // [50000, 512]
    const float* W    = (const float*)d_in[2];  // [1, 1024]
    const float* bias = (const float*)d_in[3];  // [1]
    float* out = (float*)d_out;

    int extra = out_size > OUT_ELEMS ? (out_size - OUT_ELEMS) : 0;

    // Kernel 1: (1024 + 50000) rows, 8 warps per 256-thread block.
    // Also zeroes the `extra` trailing output elements.
    {
        int total_rows = B_ROWS + E_ROWS;
        int warps_per_block = 256 / 32;
        int blocks = (total_rows + warps_per_block - 1) / warps_per_block;
        dot_kernel<<<blocks, 256>>>(hr, tail, W, bias, out + OUT_ELEMS, extra);
    }

    // Kernel 2: loop-inverted outer sum.
    {
        dim3 grid((E4 + 255) / 256, NUM_CHUNKS);
        outer_kernel<<<grid, 256>>>((float4*)out);
    }
}

// round 15
// speedup vs baseline: 1.1336x; 1.0852x over previous
#include <cuda_runtime.h>
#include <cuda_bf16.h>

#define CLASS_NUM 512
#define B_ROWS    1024
#define E_ROWS    50000
#define OUT_ELEMS (B_ROWS * E_ROWS)   // 51,200,000
#define E4        (E_ROWS / 4)        // 12,500 float4 per output row

#define ROW_CHUNK  32
#define NUM_CHUNKS (B_ROWS / ROW_CHUNK)   // 32

#define TOTAL_ROWS (B_ROWS + E_ROWS)      // 51,024
#define ROW_PAIRS  ((TOTAL_ROWS + 1) / 2) // 25,512 (one warp per pair)

// Scratch (no device allocation allowed): row partial sums.
__device__ float g_hr[B_ROWS];     // hr_part[b] + bias  (bias folded here)
__device__ float g_tail[E_ROWS];   // tail_part[e]

// ---------------------------------------------------------------------------
// Kernel 1: TWO rows per warp, loads for both rows front-batched (8 LDG.128
// in flight per warp -> double the MLP of one-row-per-warp).
// row < B_ROWS  -> g_hr[row]   = dot(hr[row],   W[0:512]) + bias
// row >= B_ROWS -> g_tail[r-B] = dot(tail[r-B], W[512:1024])
// Also zeroes any output elements beyond the scores matrix.
// ---------------------------------------------------------------------------
__global__ void __launch_bounds__(256)
dot_kernel(const float* __restrict__ hr,
           const float* __restrict__ tail,
           const float* __restrict__ W,
           const float* __restrict__ bias,
           float* __restrict__ out_extra,   // out + OUT_ELEMS
           int extra)                        // out_size - OUT_ELEMS (>= 0)
{
    const int gtid = blockIdx.x * blockDim.x + threadIdx.x;
    const int pair = gtid >> 5;
    const int lane = threadIdx.x & 31;

    if (gtid < extra)
        out_extra[gtid] = 0.0f;

    if (pair >= ROW_PAIRS) return;

    const int row0 = pair * 2;
    const int row1 = row0 + 1;                 // row1 < TOTAL_ROWS (51024 even)

    // Per-row source / weight selection.
    const float* src0 = (row0 < B_ROWS) ? hr + (size_t)row0 * CLASS_NUM
                                        : tail + (size_t)(row0 - B_ROWS) * CLASS_NUM;
    const float* src1 = (row1 < B_ROWS) ? hr + (size_t)row1 * CLASS_NUM
                                        : tail + (size_t)(row1 - B_ROWS) * CLASS_NUM;
    const float4* w0 = reinterpret_cast<const float4*>((row0 < B_ROWS) ? W : W + CLASS_NUM);
    const float4* w1 = reinterpret_cast<const float4*>((row1 < B_ROWS) ? W : W + CLASS_NUM);

    const float4* s0 = reinterpret_cast<const float4*>(src0);
    const float4* s1 = reinterpret_cast<const float4*>(src1);

    // Front-batch all 8 data loads (streaming, evict-first).
    float4 a0 = __ldcs(&s0[lane]);
    float4 a1 = __ldcs(&s0[lane + 32]);
    float4 a2 = __ldcs(&s0[lane + 64]);
    float4 a3 = __ldcs(&s0[lane + 96]);
    float4 b0 = __ldcs(&s1[lane]);
    float4 b1 = __ldcs(&s1[lane + 32]);
    float4 b2 = __ldcs(&s1[lane + 64]);
    float4 b3 = __ldcs(&s1[lane + 96]);

    // Weight loads (L1/L2-resident after first warps).
    float4 c0 = __ldg(&w0[lane]);
    float4 c1 = __ldg(&w0[lane + 32]);
    float4 c2 = __ldg(&w0[lane + 64]);
    float4 c3 = __ldg(&w0[lane + 96]);
    float4 d0 = __ldg(&w1[lane]);
    float4 d1 = __ldg(&w1[lane + 32]);
    float4 d2 = __ldg(&w1[lane + 64]);
    float4 d3 = __ldg(&w1[lane + 96]);

    float sum0 = 0.0f, sum1 = 0.0f;
    sum0 = fmaf(a0.x, c0.x, sum0); sum0 = fmaf(a0.y, c0.y, sum0);
    sum0 = fmaf(a0.z, c0.z, sum0); sum0 = fmaf(a0.w, c0.w, sum0);
    sum0 = fmaf(a1.x, c1.x, sum0); sum0 = fmaf(a1.y, c1.y, sum0);
    sum0 = fmaf(a1.z, c1.z, sum0); sum0 = fmaf(a1.w, c1.w, sum0);
    sum0 = fmaf(a2.x, c2.x, sum0); sum0 = fmaf(a2.y, c2.y, sum0);
    sum0 = fmaf(a2.z, c2.z, sum0); sum0 = fmaf(a2.w, c2.w, sum0);
    sum0 = fmaf(a3.x, c3.x, sum0); sum0 = fmaf(a3.y, c3.y, sum0);
    sum0 = fmaf(a3.z, c3.z, sum0); sum0 = fmaf(a3.w, c3.w, sum0);

    sum1 = fmaf(b0.x, d0.x, sum1); sum1 = fmaf(b0.y, d0.y, sum1);
    sum1 = fmaf(b0.z, d0.z, sum1); sum1 = fmaf(b0.w, d0.w, sum1);
    sum1 = fmaf(b1.x, d1.x, sum1); sum1 = fmaf(b1.y, d1.y, sum1);
    sum1 = fmaf(b1.z, d1.z, sum1); sum1 = fmaf(b1.w, d1.w, sum1);
    sum1 = fmaf(b2.x, d2.x, sum1); sum1 = fmaf(b2.y, d2.y, sum1);
    sum1 = fmaf(b2.z, d2.z, sum1); sum1 = fmaf(b2.w, d2.w, sum1);
    sum1 = fmaf(b3.x, d3.x, sum1); sum1 = fmaf(b3.y, d3.y, sum1);
    sum1 = fmaf(b3.z, d3.z, sum1); sum1 = fmaf(b3.w, d3.w, sum1);

    // Two warp reductions (independent -> dual-issue friendly).
#pragma unroll
    for (int off = 16; off > 0; off >>= 1) {
        sum0 += __shfl_xor_sync(0xFFFFFFFFu, sum0, off);
        sum1 += __shfl_xor_sync(0xFFFFFFFFu, sum1, off);
    }

    if (lane == 0) {
        const float bv = __ldg(bias);
        if (row0 < B_ROWS) g_hr[row0] = sum0 + bv;
        else               g_tail[row0 - B_ROWS] = sum0;
        if (row1 < B_ROWS) g_hr[row1] = sum1 + bv;
        else               g_tail[row1 - B_ROWS] = sum1;
    }
}

// ---------------------------------------------------------------------------
// Kernel 2: broadcast outer sum, LOOP-INVERTED.
// Each thread owns one float4 of tail_part (read ONCE into a register),
// then streams out[b][e4] = g_hr[b] + t for a 32-row chunk of b.
// grid: x covers e4 tiles (49), y covers row chunks (32) -> 1568 blocks.
// ---------------------------------------------------------------------------
__global__ void __launch_bounds__(256)
outer_kernel(float4* __restrict__ out)
{
    __shared__ float sh_hr[ROW_CHUNK];

    const int row0 = blockIdx.y * ROW_CHUNK;
    if (threadIdx.x < ROW_CHUNK)
        sh_hr[threadIdx.x] = g_hr[row0 + threadIdx.x];
    __syncthreads();

    const int e4 = blockIdx.x * blockDim.x + threadIdx.x;
    if (e4 >= E4) return;

    const float4 t = *((const float4*)g_tail + e4);

    float4* dst = out + (size_t)row0 * E4 + e4;
#pragma unroll 4
    for (int r = 0; r < ROW_CHUNK; r++) {
        const float h = sh_hr[r];
        float4 v;
        v.x = h + t.x;
        v.y = h + t.y;
        v.z = h + t.z;
        v.w = h + t.w;
        __stcs(dst, v);              // streaming store, evict-first
        dst += E4;
    }
}

extern "C" void kernel_launch(void* const* d_in, const int* in_sizes, int n_in,
                              void* d_out, int out_size)
{
    const float* hr   = (const float*)d_in[0];  // [1024, 512]
    const float* tail = (const float*)d_in[1];  // [50000, 512]
    const float* W    = (const float*)d_in[2];  // [1, 1024]
    const float* bias = (const float*)d_in[3];  // [1]
    float* out = (float*)d_out;

    int extra = out_size > OUT_ELEMS ? (out_size - OUT_ELEMS) : 0;

    // Kernel 1: one warp per row PAIR (8 warps / 256-thread block).
    {
        int blocks = (ROW_PAIRS * 32 + 255) / 256;
        dot_kernel<<<blocks, 256>>>(hr, tail, W, bias, out + OUT_ELEMS, extra);
    }

    // Kernel 2: loop-inverted outer sum, 32-row chunks.
    {
        dim3 grid((E4 + 255) / 256, NUM_CHUNKS);
        outer_kernel<<<grid, 256>>>((float4*)out);
    }
}